// round 5
// baseline (speedup 1.0000x reference)
#include <cuda_runtime.h>
#include <math.h>

#define Xd 32
#define Yd 16
#define Nn 8192          // 32*16*16
#define Cc 4
#define NITER 5
#define ALPHA 5.0f
#define BETA  5.0f
#define GAMMA 5.0f
#define DEG 7            // total-degree Taylor truncation for exp(f.f')
#define RK 36            // #(i,j), i+j<=7
#define NBLK (RK * Cc + Cc)   // 148 blocks == co-resident on 152 SMs
#define SMEM_FLOATS (2 * Nn + 160)
#define SMEM_BYTES (SMEM_FLOATS * 4)

// ---- static device scratch (no allocations anywhere) ----
__device__ float g_phi[RK][Nn];      // phi, scaled in place to psi = phi*pre1
__device__ float g_e[Nn];
__device__ float g_pre1[Nn];
__device__ float g_pre2[Nn];
__device__ float g_part[NBLK][Nn];   // per-(rank,channel) partials
__device__ float g_q[2][Cc][Nn];     // q ping-pong, planar
__device__ unsigned g_arr[NBLK];     // per-block arrival flags (monotonic)
__device__ unsigned g_gen;           // published generation (monotonic)

// ---- contention-free grid barrier: flag array + single observer block ----
__device__ __forceinline__ void gbar(unsigned tgt, int b, int tid) {
    __syncthreads();
    if (b == 0) {
        if (tid == 0) { __threadfence(); *(volatile unsigned*)&g_arr[0] = tgt; }
        if (tid < NBLK) {
            while (*(volatile unsigned*)&g_arr[tid] < tgt) { }
        }
        __syncthreads();
        if (tid == 0) { __threadfence(); *(volatile unsigned*)&g_gen = tgt; }
    } else {
        if (tid == 0) {
            __threadfence();
            *(volatile unsigned*)&g_arr[b] = tgt;
            while (*(volatile unsigned*)&g_gen < tgt) { }
            __threadfence();
        }
        __syncthreads();
    }
}

// ---- separable 3D Gaussian conv over 32x16x16 field in shared memory ----
// input sa, result sb (sa clobbered). All branches warp-uniform.
__device__ __forceinline__ void conv3d(float* sa, float* sb,
                                       const float* wx, const float* wyz, int tid) {
    __syncthreads();
    // conv-x: sa -> sb (32 taps, stride 256), rolling weight registers
    {
        int warp = tid >> 5, lane = tid & 31;
        int xg = (warp >> 2) << 2;
        int yz = ((warp & 3) << 6) + (lane << 1);
        float2 a0 = {0.f,0.f}, a1 = {0.f,0.f}, a2 = {0.f,0.f}, a3 = {0.f,0.f};
        float w0 = wx[xg], w1 = wx[xg + 1], w2 = wx[xg + 2], w3 = wx[xg + 3];
#pragma unroll
        for (int xp = 0; xp < Xd; xp++) {
            float2 v = *(const float2*)(sa + (xp << 8) + yz);
            a0.x += w0 * v.x; a0.y += w0 * v.y;
            a1.x += w1 * v.x; a1.y += w1 * v.y;
            a2.x += w2 * v.x; a2.y += w2 * v.y;
            a3.x += w3 * v.x; a3.y += w3 * v.y;
            if (xp < Xd - 1) {
                w3 = w2; w2 = w1; w1 = w0;
                int d = xg - xp - 1;
                w0 = wx[d < 0 ? -d : d];
            }
        }
        *(float2*)(sb + ((xg + 0) << 8) + yz) = a0;
        *(float2*)(sb + ((xg + 1) << 8) + yz) = a1;
        *(float2*)(sb + ((xg + 2) << 8) + yz) = a2;
        *(float2*)(sb + ((xg + 3) << 8) + yz) = a3;
    }
    __syncthreads();
    // conv-y: sb -> sa (16 taps, stride 16). 2 threads/line, half = tid>>9 (warp-uniform)
    {
        int line = tid & 511, half = tid >> 9;
        int z = line & 15, x = line >> 4;
        int base = (x << 8) + z;
        float lin[16], wv[16];
#pragma unroll
        for (int y = 0; y < Yd; y++) lin[y] = sb[base + (y << 4)];
#pragma unroll
        for (int d = 0; d < Yd; d++) wv[d] = wyz[d];
        if (half == 0) {
#pragma unroll
            for (int yo = 0; yo < 8; yo++) {
                float s = 0.f;
#pragma unroll
                for (int yp = 0; yp < Yd; yp++)
                    s += wv[(yo > yp) ? (yo - yp) : (yp - yo)] * lin[yp];
                sa[base + (yo << 4)] = s;
            }
        } else {
#pragma unroll
            for (int yo = 8; yo < 16; yo++) {
                float s = 0.f;
#pragma unroll
                for (int yp = 0; yp < Yd; yp++)
                    s += wv[(yo > yp) ? (yo - yp) : (yp - yo)] * lin[yp];
                sa[base + (yo << 4)] = s;
            }
        }
    }
    __syncthreads();
    // conv-z: sa -> sb (16 taps, stride 1). 2 threads/line, half = tid>>9
    {
        int line = tid & 511, half = tid >> 9;
        float l[16], wv[16];
        const float4* L4 = (const float4*)(sa + line * 16);
#pragma unroll
        for (int i = 0; i < 4; i++) {
            float4 v = L4[i];
            l[4*i] = v.x; l[4*i+1] = v.y; l[4*i+2] = v.z; l[4*i+3] = v.w;
        }
#pragma unroll
        for (int d = 0; d < Yd; d++) wv[d] = wyz[d];
        float o[8];
        if (half == 0) {
#pragma unroll
            for (int zo = 0; zo < 8; zo++) {
                float s = 0.f;
#pragma unroll
                for (int zp = 0; zp < 16; zp++)
                    s += wv[(zo > zp) ? (zo - zp) : (zp - zo)] * l[zp];
                o[zo] = s;
            }
        } else {
#pragma unroll
            for (int zo = 8; zo < 16; zo++) {
                float s = 0.f;
#pragma unroll
                for (int zp = 0; zp < 16; zp++)
                    s += wv[(zo > zp) ? (zo - zp) : (zp - zo)] * l[zp];
                o[zo - 8] = s;
            }
        }
        float4* O4 = (float4*)(sb + line * 16 + half * 8);
        O4[0] = make_float4(o[0], o[1], o[2], o[3]);
        O4[1] = make_float4(o[4], o[5], o[6], o[7]);
    }
    __syncthreads();
}

__global__ __launch_bounds__(1024, 1) void k_crf(
    const float* __restrict__ lu, const float* __restrict__ fp,
    const float* __restrict__ comp, float* __restrict__ out) {
    extern __shared__ float sm[];
    float* s_a   = sm;
    float* s_b   = sm + Nn;
    float* s_wax = sm + 2 * Nn;        // 32
    float* s_way = s_wax + 32;         // 16
    float* s_wgx = s_way + 16;         // 32
    float* s_wgy = s_wgx + 32;         // 16
    float* s_cmp = s_wgy + 16;         // 16
    __shared__ unsigned s_base;

    int tid = threadIdx.x;
    int b = blockIdx.x;

    if (tid == 0) s_base = *(volatile unsigned*)&g_arr[b];  // own flag: replay-safe base
    if (tid < 32) {
        float d2 = (float)tid * (float)tid;
        s_wax[tid] = __expf(-0.5f * d2 / (ALPHA * ALPHA));
        s_wgx[tid] = __expf(-0.5f * d2 / (GAMMA * GAMMA));
    }
    if (tid < 16) {
        float d2 = (float)tid * (float)tid;
        s_way[tid] = __expf(-0.5f * d2 / (ALPHA * ALPHA));
        s_wgy[tid] = __expf(-0.5f * d2 / (GAMMA * GAMMA));
        s_cmp[tid] = comp[tid];
    }
    __syncthreads();
    unsigned base = s_base, bk = 0;

    // ---- phase A: features, phi basis, q0 = softmax(lu) ----
    if (b < 8) {
        int n = (b << 10) + tid;
        float fa = fp[n] * (1.0f / BETA);
        float fb = fp[Nn + n] * (1.0f / BETA);
        float e = __expf(-0.5f * (fa * fa + fb * fb));
        g_e[n] = e;
        float fi = 1.f, pai = 1.f;
        int r = 0;
#pragma unroll
        for (int i = 0; i <= DEG; i++) {
            if (i > 0) fi *= (float)i;
            float fj = 1.f, pbj = 1.f;
#pragma unroll
            for (int j = 0; j <= DEG - i; j++) {
                if (j > 0) fj *= (float)j;
                g_phi[r][n] = rsqrtf(fi * fj) * pai * pbj;
                pbj *= fb;
                r++;
            }
            pai *= fa;
        }
        float l0 = lu[n], l1 = lu[Nn + n], l2 = lu[2 * Nn + n], l3 = lu[3 * Nn + n];
        float mx = fmaxf(fmaxf(l0, l1), fmaxf(l2, l3));
        float e0 = __expf(l0 - mx), e1 = __expf(l1 - mx);
        float e2 = __expf(l2 - mx), e3 = __expf(l3 - mx);
        float inv = 1.0f / (e0 + e1 + e2 + e3);
        g_q[0][0][n] = e0 * inv; g_q[0][1][n] = e1 * inv;
        g_q[0][2][n] = e2 * inv; g_q[0][3][n] = e3 * inv;
    }
    gbar(base + (++bk), b, tid);

    // ---- phase B: bilateral rowsums (blocks 0..RK-1) ----
    if (b < RK) {
        const float4* phi4 = (const float4*)g_phi[b];
        const float4* e4 = (const float4*)g_e;
        float4* sa4 = (float4*)s_a;
#pragma unroll
        for (int u = 0; u < 2; u++) {
            int i4 = tid * 2 + u;
            float4 A = phi4[i4], E = e4[i4];
            sa4[i4] = make_float4(A.x * E.x, A.y * E.y, A.z * E.z, A.w * E.w);
        }
        conv3d(s_a, s_b, s_wax, s_way, tid);
        const float4* sb4 = (const float4*)s_b;
        float4* dst = (float4*)g_part[b];
#pragma unroll
        for (int u = 0; u < 2; u++) {
            int i4 = tid * 2 + u;
            float4 A = phi4[i4], V = sb4[i4];
            dst[i4] = make_float4(A.x * V.x, A.y * V.y, A.z * V.z, A.w * V.w);
        }
    }
    gbar(base + (++bk), b, tid);

    // ---- phase C: normalization scales (distributed: 32 blocks x 256 threads) ----
    if (b < 32 && tid < 256) {
        int n = (b << 8) + tid;
        float s = 0.f;
#pragma unroll
        for (int r = 0; r < RK; r++) s += __ldcg(&g_part[r][n]);
        float e = g_e[n];
        g_pre1[n] = e * rsqrtf(e * s);
        int x = n >> 8, y = (n >> 4) & 15, z = n & 15;
        float Rx = 0.f, Ry = 0.f, Rz = 0.f;
#pragma unroll
        for (int d = 0; d < Xd; d++) Rx += s_wgx[(x > d) ? (x - d) : (d - x)];
#pragma unroll
        for (int d = 0; d < Yd; d++) {
            Ry += s_wgy[(y > d) ? (y - d) : (d - y)];
            Rz += s_wgy[(z > d) ? (z - d) : (d - z)];
        }
        g_pre2[n] = rsqrtf(Rx * Ry * Rz);
    }
    gbar(base + (++bk), b, tid);

    // ---- phase D: psi = phi * pre1 in place ----
    if (b < RK) {
#pragma unroll
        for (int u = 0; u < 8; u++) {
            int n = (u << 10) + tid;
            g_phi[b][n] *= g_pre1[n];
        }
    }
    gbar(base + (++bk), b, tid);

    // ---- phase E: 5 mean-field iterations ----
    int r = b >> 2, c = b & 3;
    bool sp = (r == RK);
    const float4* mul4 = sp ? (const float4*)g_pre2 : (const float4*)g_phi[r];
    const float* wxE = sp ? s_wgx : s_wax;
    const float* wyE = sp ? s_wgy : s_way;
    for (int it = 0; it < NITER; it++) {
        // conv: all 148 blocks busy
        {
            const float4* q4 = (const float4*)g_q[it & 1][c];
            float4* sa4 = (float4*)s_a;
#pragma unroll
            for (int u = 0; u < 2; u++) {
                int i4 = tid * 2 + u;
                float4 M = __ldcg(mul4 + i4);
                float4 Q = __ldcg(q4 + i4);
                sa4[i4] = make_float4(M.x * Q.x, M.y * Q.y, M.z * Q.z, M.w * Q.w);
            }
            conv3d(s_a, s_b, wxE, wyE, tid);
            const float4* sb4 = (const float4*)s_b;
            float4* dst = (float4*)g_part[b];
#pragma unroll
            for (int u = 0; u < 2; u++) {
                int i4 = tid * 2 + u;
                float4 M = __ldcg(mul4 + i4);
                float4 V = sb4[i4];
                dst[i4] = make_float4(M.x * V.x, M.y * V.y, M.z * V.z, M.w * V.w);
            }
        }
        gbar(base + (++bk), b, tid);
        // update (distributed): 128 blocks x 256 threads, one (n,c) per thread
        if (b < 128 && tid < 256) {
            int idx = (b << 8) + tid;
            int cc = idx & 3, n = idx >> 2;
            float u = 0.f;
#pragma unroll
            for (int k = 0; k <= RK; k++)
                u += __ldcg(&g_part[k * 4 + cc][n]);
            float v1 = __shfl_xor_sync(0xFFFFFFFFu, u, 1);
            float v2 = __shfl_xor_sync(0xFFFFFFFFu, u, 2);
            float v3 = __shfl_xor_sync(0xFFFFFFFFu, u, 3);
            float qu = s_cmp[cc * 4 + cc] * u
                     + s_cmp[cc * 4 + (cc ^ 1)] * v1
                     + s_cmp[cc * 4 + (cc ^ 2)] * v2
                     + s_cmp[cc * 4 + (cc ^ 3)] * v3;
            float lg = lu[cc * Nn + n] - qu;
            float m1 = fmaxf(lg, __shfl_xor_sync(0xFFFFFFFFu, lg, 1));
            float mx = fmaxf(m1, __shfl_xor_sync(0xFFFFFFFFu, m1, 2));
            float e = __expf(lg - mx);
            float s1 = e + __shfl_xor_sync(0xFFFFFFFFu, e, 1);
            float ss = s1 + __shfl_xor_sync(0xFFFFFFFFu, s1, 2);
            float qv = e / ss;
            if (it == NITER - 1) out[cc * Nn + n] = qv;
            else                 g_q[(it + 1) & 1][cc][n] = qv;
        }
        if (it < NITER - 1) gbar(base + (++bk), b, tid);
    }
}

extern "C" void kernel_launch(void* const* d_in, const int* in_sizes, int n_in,
                              void* d_out, int out_size) {
    const float* lu   = (const float*)d_in[0];
    const float* fp   = (const float*)d_in[1];
    const float* comp = (const float*)d_in[2];
    float* out = (float*)d_out;

    cudaFuncSetAttribute(k_crf, cudaFuncAttributeMaxDynamicSharedMemorySize, SMEM_BYTES);
    k_crf<<<NBLK, 1024, SMEM_BYTES>>>(lu, fp, comp, out);
}